// round 9
// baseline (speedup 1.0000x reference)
#include <cuda_runtime.h>
#include <math.h>

#define BATCH   2048
#define NPIX    784
#define NMID    783      // number of mid cores
#define NSEG    16
#define LSEG    49       // NSEG*LSEG = 784 >= 783 (1 identity pad)
#define UPB     64       // batch units per block (phase 1)
#define T1      128      // threads per block (phase 1): 2 threads per unit
#define CB      4        // batches (warps) per block in combine
#define SLOT    105      // padded matrix slot (odd word stride -> bank spread)
#define CH0     24       // staging chunk sizes (24 + 25 = 49 steps)
#define CH1     25

// 4x pre-scale keeps segment-product norms in mid fp32 range.
#define MSCALE      4.0f
#define SEG_LOGCOMP 67.92842369489701f   // LSEG * ln(4), subtracted exactly

typedef unsigned long long u64;

// Scratch: per (segment, batch) normalized 10x10 product + log norm
__device__ __align__(16) float g_G[(size_t)NSEG * BATCH * 100];  // [seg][b][l*10+h]
__device__ float g_logn[NSEG * BATCH];                            // [seg][b]

// ---- packed f32x2 helpers ----
__device__ __forceinline__ u64 ffma2(u64 a, u64 b, u64 c) {
    u64 d; asm("fma.rn.f32x2 %0, %1, %2, %3;" : "=l"(d) : "l"(a), "l"(b), "l"(c));
    return d;
}
__device__ __forceinline__ u64 fmul2(u64 a, u64 b) {
    u64 d; asm("mul.rn.f32x2 %0, %1, %2;" : "=l"(d) : "l"(a), "l"(b));
    return d;
}
__device__ __forceinline__ u64 pk2(float lo, float hi) {
    u64 r; asm("mov.b64 %0, {%1, %2};" : "=l"(r) : "f"(lo), "f"(hi));
    return r;
}
__device__ __forceinline__ void upk2(u64 v, float& lo, float& hi) {
    asm("mov.b64 {%0, %1}, %2;" : "=f"(lo), "=f"(hi) : "l"(v));
}

// Stage steps [cs, cs+clen) of this segment into dup-format shared:
// per (step,k): 40 floats = [ (A,A) x10h | (D,D) x10h ], all pre-scaled.
__device__ __forceinline__ void stage(float* __restrict__ sAD,
                                      const float* __restrict__ cm,
                                      int n0, int cs, int clen, int tid) {
    for (int idx = tid; idx < clen * 400; idx += T1) {
        const int r    = idx % 400;
        const int step = idx / 400;
        const int k    = r / 40;
        const int j    = r % 40;
        const int h    = ((j < 20) ? j : (j - 20)) >> 1;
        const int n    = n0 + cs + step;
        float val;
        if (n < NMID) {
            const int base = ((n * 10 + k) * 2) * 10;   // f=0 row
            const float a = cm[base + h];
            val = (j < 20) ? (MSCALE * a) : (MSCALE * (cm[base + 10 + h] - a));
        } else {
            val = (j < 20 && h == k) ? MSCALE : 0.0f;   // scaled identity pad
        }
        sAD[idx] = val;
    }
}

// One chain step, row-pair packed, MOV-free:
//   Q[(r0,r1)][h] = sum_k (P[r0][k],P[r1][k]) .* (m[k][h],m[k][h])
// where the dup pair (m,m) is built by ONE ffma2 from dup-format shared.
__device__ __forceinline__ void stepmul2(const float* __restrict__ s, u64 xx,
                                         const u64 (&P)[3][10], u64 (&Q)[3][10]) {
    #pragma unroll
    for (int k = 0; k < 10; ++k) {
        const u64* ad = reinterpret_cast<const u64*>(s + k * 40);
        u64 md[10];
        #pragma unroll
        for (int h = 0; h < 10; ++h) md[h] = ffma2(xx, ad[10 + h], ad[h]);
        #pragma unroll
        for (int p = 0; p < 3; ++p) {
            const u64 pv = P[p][k];
            if (k == 0) {
                #pragma unroll
                for (int h = 0; h < 10; ++h) Q[p][h] = fmul2(pv, md[h]);
            } else {
                #pragma unroll
                for (int h = 0; h < 10; ++h) Q[p][h] = ffma2(pv, md[h], Q[p][h]);
            }
        }
    }
}

// Phase 1: per (batch, segment) normalized product of the segment's matrices.
// Matrix zero-padded to 12 rows: thread half owns rows rbase..rbase+5 as 3
// row-pairs (rows 10,11 identically zero -> inert). P starts as identity.
__global__ void __launch_bounds__(T1, 3)
phase1(const float* __restrict__ x, const float* __restrict__ cm) {
    __shared__ __align__(16) float sAD[CH1 * 400];   // 40 KB

    const int seg = blockIdx.x;
    const int n0  = seg * LSEG;
    const int t    = threadIdx.x;
    const int unit = t >> 1;
    const int half = t & 1;
    const int b    = blockIdx.y * UPB + unit;
    const float* xb = x + (size_t)b * NPIX;
    const int rbase = half * 6;

    u64 P[3][10], Q[3][10];
    #pragma unroll
    for (int p = 0; p < 3; ++p)
        #pragma unroll
        for (int k = 0; k < 10; ++k)
            P[p][k] = pk2((rbase + 2 * p == k) ? 1.0f : 0.0f,
                          (rbase + 2 * p + 1 == k) ? 1.0f : 0.0f);

    // ---- chunk 0: steps 0..23 ----
    stage(sAD, cm, n0, 0, CH0, t);
    __syncthreads();
    #pragma unroll 1
    for (int st = 0; st < CH0; st += 2) {
        const float x0 = xb[n0 + st + 1];        // max 759 < NPIX, no clamp
        const float x1 = xb[n0 + st + 2];
        stepmul2(sAD + st * 400, pk2(x0, x0), P, Q);
        stepmul2(sAD + (st + 1) * 400, pk2(x1, x1), Q, P);
    }
    __syncthreads();

    // ---- chunk 1: steps 24..48 ----
    stage(sAD, cm, n0, CH0, CH1, t);
    __syncthreads();
    #pragma unroll 1
    for (int st = 0; st < 24; st += 2) {
        const int g = n0 + CH0 + st;
        const float x0 = xb[min(g + 1, NPIX - 1)];
        const float x1 = xb[min(g + 2, NPIX - 1)];
        stepmul2(sAD + st * 400, pk2(x0, x0), P, Q);
        stepmul2(sAD + (st + 1) * 400, pk2(x1, x1), Q, P);
    }
    {   // final step 48 (local 24) -> result lands in Q
        const float x0 = xb[min(n0 + LSEG, NPIX - 1)];
        stepmul2(sAD + 24 * 400, pk2(x0, x0), P, Q);
    }

    // Frobenius norm over both halves (pair reduction), normalize, store.
    u64 ss2 = 0ull;
    #pragma unroll
    for (int p = 0; p < 3; ++p)
        #pragma unroll
        for (int h = 0; h < 10; ++h) ss2 = ffma2(Q[p][h], Q[p][h], ss2);
    float slo, shi;
    upk2(ss2, slo, shi);
    float ss = slo + shi;
    ss += __shfl_xor_sync(0xffffffffu, ss, 1);
    ss = fmaxf(ss, 1e-24f);

    const float inv = rsqrtf(ss);
    const u64 ii = pk2(inv, inv);

    float* gp = g_G + ((size_t)seg * BATCH + b) * 100;
    #pragma unroll
    for (int p = 0; p < 3; ++p) {
        const int r0 = rbase + 2 * p;
        const int r1 = r0 + 1;
        #pragma unroll
        for (int h = 0; h < 10; ++h) {
            float lo, hi;
            upk2(fmul2(Q[p][h], ii), lo, hi);
            if (r0 < 10) gp[r0 * 10 + h] = lo;
            if (r1 < 10) gp[r1 * 10 + h] = hi;
        }
    }
    if (half == 0)
        g_logn[seg * BATCH + b] = 0.5f * __logf(ss) - SEG_LOGCOMP;
}

// Combine: one warp per batch, binary tree 16->8->4->2->1 (verified 12.9us
// in round 5 — unchanged).
__global__ void __launch_bounds__(CB * 32)
combine(const float* __restrict__ x, const float* __restrict__ core0,
        const float* __restrict__ cls, float* __restrict__ out) {
    __shared__ float sG[CB][24][SLOT];
    __shared__ float sW[CB][10];

    const int w    = threadIdx.x >> 5;
    const int lane = threadIdx.x & 31;
    const int b    = blockIdx.x * CB + w;

    float logacc = 0.0f;

    #pragma unroll
    for (int s = 0; s < NSEG; ++s) {
        const float* src = g_G + ((size_t)s * BATCH + b) * 100;
        #pragma unroll
        for (int i = lane; i < 100; i += 32) sG[w][s][i] = src[i];
    }
    #pragma unroll
    for (int s = 0; s < 24; ++s)
        if (lane < SLOT - 100) sG[w][s][100 + lane] = 0.0f;
    if (lane < NSEG) logacc = g_logn[lane * BATCH + b];
    __syncwarp();

    const int in0[4]  = {0, 16, 0, 4};
    const int out0[4] = {16, 0, 4, 6};
    const int cnt[4]  = {8, 4, 2, 1};

    #pragma unroll
    for (int lev = 0; lev < 4; ++lev) {
        const int L  = 32 / cnt[lev];
        const int p  = lane / L;
        const int lg = lane % L;
        const unsigned gm = (L == 32) ? 0xffffffffu
                                      : (((1u << L) - 1u) << (p * L));
        const float* A  = sG[w][in0[lev] + 2 * p];
        const float* Bm = sG[w][in0[lev] + 2 * p + 1];
        float* C = sG[w][out0[lev] + p];

        bool  vld[3];
        int   hx[3];
        #pragma unroll
        for (int i = 0; i < 3; ++i) {
            const int h = lg + i * L;
            vld[i] = (h < 10);
            hx[i]  = vld[i] ? h : 0;
        }

        float c[10][3];
        #pragma unroll
        for (int l = 0; l < 10; ++l)
            #pragma unroll
            for (int i = 0; i < 3; ++i) c[l][i] = 0.0f;

        #pragma unroll
        for (int k = 0; k < 10; ++k) {
            float bk[3];
            #pragma unroll
            for (int i = 0; i < 3; ++i) bk[i] = Bm[k * 10 + hx[i]];
            #pragma unroll
            for (int l = 0; l < 10; ++l) {
                const float av = A[l * 10 + k];
                #pragma unroll
                for (int i = 0; i < 3; ++i) c[l][i] = fmaf(av, bk[i], c[l][i]);
            }
        }

        float ss = 0.0f;
        #pragma unroll
        for (int l = 0; l < 10; ++l)
            #pragma unroll
            for (int i = 0; i < 3; ++i)
                if (vld[i]) ss = fmaf(c[l][i], c[l][i], ss);
        #pragma unroll
        for (int off = 16; off >= 1; off >>= 1)
            if (off < L) ss += __shfl_xor_sync(gm, ss, off);

        ss = fmaxf(ss, 1e-24f);
        const float inv = rsqrtf(ss);
        if (lg == 0) logacc += 0.5f * __logf(ss);

        #pragma unroll
        for (int l = 0; l < 10; ++l)
            #pragma unroll
            for (int i = 0; i < 3; ++i)
                if (vld[i]) C[l * 10 + lg + i * L] = c[l][i] * inv;
        __syncwarp();
    }

    const float x0 = x[(size_t)b * NPIX];
    float wv = 0.0f;
    if (lane < 10) {
        #pragma unroll
        for (int l = 0; l < 10; ++l) {
            const float v0l = fmaf(x0, core0[10 + l] - core0[l], core0[l]);
            wv = fmaf(v0l, sG[w][6][l * 10 + lane], wv);
        }
    }
    float sq = (lane < 10) ? wv * wv : 0.0f;
    #pragma unroll
    for (int o = 16; o >= 1; o >>= 1) sq += __shfl_xor_sync(0xffffffffu, sq, o);
    #pragma unroll
    for (int o = 16; o >= 1; o >>= 1) logacc += __shfl_xor_sync(0xffffffffu, logacc, o);

    sq = fmaxf(sq, 1e-24f);
    const float logtot = logacc + 0.5f * __logf(sq);
    const float inv = rsqrtf(sq);
    if (lane < 10) sW[w][lane] = wv * inv;
    __syncwarp();

    if (lane < 10) {
        float acc = 0.0f;
        #pragma unroll
        for (int h = 0; h < 10; ++h) acc = fmaf(sW[w][h], cls[lane * 10 + h], acc);
        out[(size_t)b * 10 + lane] = acc + logtot;
    }
}

// Three dummies pad the per-call launch count to 5 so the fixed
// `ncu -s 5 -c 1` capture (6th launch overall) lands on call 2's phase1.
__global__ void dummyk() {}

extern "C" void kernel_launch(void* const* d_in, const int* in_sizes, int n_in,
                              void* d_out, int out_size) {
    const float* x     = (const float*)d_in[0];   // (2048, 784)
    const float* core0 = (const float*)d_in[1];   // (1, 2, 10)
    const float* cm    = (const float*)d_in[2];   // (783, 10, 2, 10)
    const float* cls   = (const float*)d_in[3];   // (10, 10)
    float* out = (float*)d_out;                   // (2048, 10)

    dim3 g1(NSEG, BATCH / UPB);
    phase1<<<g1, T1>>>(x, cm);
    combine<<<BATCH / CB, CB * 32>>>(x, core0, cls, out);
    dummyk<<<1, 32>>>();
    dummyk<<<1, 32>>>();
    dummyk<<<1, 32>>>();
}

// round 11
// speedup vs baseline: 1.2647x; 1.2647x over previous
#include <cuda_runtime.h>
#include <math.h>

#define BATCH   2048
#define NPIX    784
#define NMID    783      // number of mid cores
#define NSEG    16
#define LSEG    49       // NSEG*LSEG = 784 >= 783 (1 identity pad)
#define UPB     64       // batch units per block (phase 1)
#define T1      128      // threads per block (phase 1): 2 threads per unit
#define CB      4        // batches (warps) per block in combine
#define SLOT    105      // padded matrix slot (odd word stride -> bank spread)

// 4x pre-scale keeps segment-product norms in mid fp32 range.
#define MSCALE      4.0f
#define SEG_LOGCOMP 67.92842369489701f   // LSEG * ln(4), subtracted exactly

// Scratch: per (segment, batch) normalized 10x10 product + log norm
__device__ __align__(16) float g_G[(size_t)NSEG * BATCH * 100];  // [seg][b][l*10+h]
__device__ float g_logn[NSEG * BATCH];                            // [seg][b]

// One chain step: Q = P * M (this thread's 5 rows), M[k][h] = A[k][h] + x*D[k][h].
// Row layout in shared (per k, 24 floats, 16B-aligned): [0..9]=A, [12..21]=D.
// Scalar FFMA throughout (measured: fma.rn.f32x2 issues at rt~4 on sm_103a ->
// no gain over scalar; rounds 5/9 A/B). Vector LDS for the A/D rows.
__device__ __forceinline__ void stepmul(const float* __restrict__ s, float xv,
                                        const float (&P)[5][10], float (&Q)[5][10]) {
    #pragma unroll
    for (int k = 0; k < 10; ++k) {
        const float* row = s + k * 24;
        const float4 a0 = *reinterpret_cast<const float4*>(row);
        const float4 a1 = *reinterpret_cast<const float4*>(row + 4);
        const float2 a2 = *reinterpret_cast<const float2*>(row + 8);
        const float4 d0 = *reinterpret_cast<const float4*>(row + 12);
        const float4 d1 = *reinterpret_cast<const float4*>(row + 16);
        const float2 d2 = *reinterpret_cast<const float2*>(row + 20);

        float m[10];
        m[0] = fmaf(xv, d0.x, a0.x);
        m[1] = fmaf(xv, d0.y, a0.y);
        m[2] = fmaf(xv, d0.z, a0.z);
        m[3] = fmaf(xv, d0.w, a0.w);
        m[4] = fmaf(xv, d1.x, a1.x);
        m[5] = fmaf(xv, d1.y, a1.y);
        m[6] = fmaf(xv, d1.z, a1.z);
        m[7] = fmaf(xv, d1.w, a1.w);
        m[8] = fmaf(xv, d2.x, a2.x);
        m[9] = fmaf(xv, d2.y, a2.y);

        #pragma unroll
        for (int l = 0; l < 5; ++l) {
            const float p = P[l][k];
            if (k == 0) {
                #pragma unroll
                for (int h = 0; h < 10; ++h) Q[l][h] = p * m[h];
            } else {
                #pragma unroll
                for (int h = 0; h < 10; ++h) Q[l][h] = fmaf(p, m[h], Q[l][h]);
            }
        }
    }
}

// Phase 1: per (batch, segment) normalized product of the segment's matrices.
// Thread pair (2u, 2u+1) owns rows 0-4 / 5-9 of the running product.
__global__ void __launch_bounds__(T1, 3)
phase1(const float* __restrict__ x, const float* __restrict__ cm) {
    __shared__ __align__(16) float sAD[LSEG * 240];

    const int seg = blockIdx.x;
    const int n0  = seg * LSEG;

    // Stage MSCALE*A and MSCALE*(B-A); pad with MSCALE*identity beyond NMID.
    for (int idx = threadIdx.x; idx < LSEG * 200; idx += T1) {
        const int step = idx / 200;
        const int r    = idx % 200;
        const int k    = r / 20;
        const int j    = r % 20;          // 0..9 -> A[h], 10..19 -> D[h]
        const int n    = n0 + step;
        float val;
        if (n < NMID) {
            const int base = ((n * 10 + k) * 2) * 10;   // f=0 row
            if (j < 10) val = MSCALE * cm[base + j];
            else        val = MSCALE * (cm[base + 10 + (j - 10)] - cm[base + (j - 10)]);
        } else {
            val = (j < 10) ? ((j == k) ? MSCALE : 0.0f) : 0.0f;
        }
        sAD[step * 240 + k * 24 + ((j < 10) ? j : (j - 10 + 12))] = val;
    }
    __syncthreads();

    const int t    = threadIdx.x;
    const int unit = t >> 1;
    const int half = t & 1;
    const int b    = blockIdx.y * UPB + unit;
    const float* xb = x + (size_t)b * NPIX;

    float P[5][10], Q[5][10];

    // Load the segment's first matrix (rows half*5 .. half*5+4) directly as P.
    {
        const float xv = xb[min(n0 + 1, NPIX - 1)];
        #pragma unroll
        for (int l = 0; l < 5; ++l) {
            const float* row = sAD + (half * 5 + l) * 24;
            #pragma unroll
            for (int h = 0; h < 10; ++h)
                P[l][h] = fmaf(xv, row[12 + h], row[h]);
        }
    }

    // 48 more multiplies (even count -> result lands back in P). x prefetched.
    float xc = xb[min(n0 + 2, NPIX - 1)];
    #pragma unroll 1
    for (int st = 1; st < LSEG; st += 2) {
        const float xn1 = xb[min(n0 + st + 2, NPIX - 1)];
        const float xn2 = xb[min(n0 + st + 3, NPIX - 1)];
        stepmul(sAD + st * 240, xc, P, Q);
        stepmul(sAD + (st + 1) * 240, xn1, Q, P);
        xc = xn2;
    }

    // Frobenius norm over both halves (pair reduction), normalize, store.
    float ss = 0.0f;
    #pragma unroll
    for (int l = 0; l < 5; ++l)
        #pragma unroll
        for (int h = 0; h < 10; ++h) ss = fmaf(P[l][h], P[l][h], ss);
    ss += __shfl_xor_sync(0xffffffffu, ss, 1);
    ss = fmaxf(ss, 1e-24f);

    const float inv = rsqrtf(ss);

    float* gp = g_G + ((size_t)seg * BATCH + b) * 100 + half * 50;
    #pragma unroll
    for (int l = 0; l < 5; ++l)
        #pragma unroll
        for (int h = 0; h < 10; h += 2) {
            float2 v2 = make_float2(P[l][h] * inv, P[l][h + 1] * inv);
            *reinterpret_cast<float2*>(gp + l * 10 + h) = v2;
        }
    if (half == 0)
        g_logn[seg * BATCH + b] = 0.5f * __logf(ss) - SEG_LOGCOMP;
}

// Combine: one warp per batch, binary tree 16->8->4->2->1 (verified 12.9us
// in round 5 — unchanged).
__global__ void __launch_bounds__(CB * 32)
combine(const float* __restrict__ x, const float* __restrict__ core0,
        const float* __restrict__ cls, float* __restrict__ out) {
    __shared__ float sG[CB][24][SLOT];
    __shared__ float sW[CB][10];

    const int w    = threadIdx.x >> 5;
    const int lane = threadIdx.x & 31;
    const int b    = blockIdx.x * CB + w;

    float logacc = 0.0f;

    #pragma unroll
    for (int s = 0; s < NSEG; ++s) {
        const float* src = g_G + ((size_t)s * BATCH + b) * 100;
        #pragma unroll
        for (int i = lane; i < 100; i += 32) sG[w][s][i] = src[i];
    }
    #pragma unroll
    for (int s = 0; s < 24; ++s)
        if (lane < SLOT - 100) sG[w][s][100 + lane] = 0.0f;
    if (lane < NSEG) logacc = g_logn[lane * BATCH + b];
    __syncwarp();

    const int in0[4]  = {0, 16, 0, 4};
    const int out0[4] = {16, 0, 4, 6};
    const int cnt[4]  = {8, 4, 2, 1};

    #pragma unroll
    for (int lev = 0; lev < 4; ++lev) {
        const int L  = 32 / cnt[lev];
        const int p  = lane / L;
        const int lg = lane % L;
        const unsigned gm = (L == 32) ? 0xffffffffu
                                      : (((1u << L) - 1u) << (p * L));
        const float* A  = sG[w][in0[lev] + 2 * p];
        const float* Bm = sG[w][in0[lev] + 2 * p + 1];
        float* C = sG[w][out0[lev] + p];

        bool  vld[3];
        int   hx[3];
        #pragma unroll
        for (int i = 0; i < 3; ++i) {
            const int h = lg + i * L;
            vld[i] = (h < 10);
            hx[i]  = vld[i] ? h : 0;
        }

        float c[10][3];
        #pragma unroll
        for (int l = 0; l < 10; ++l)
            #pragma unroll
            for (int i = 0; i < 3; ++i) c[l][i] = 0.0f;

        #pragma unroll
        for (int k = 0; k < 10; ++k) {
            float bk[3];
            #pragma unroll
            for (int i = 0; i < 3; ++i) bk[i] = Bm[k * 10 + hx[i]];
            #pragma unroll
            for (int l = 0; l < 10; ++l) {
                const float av = A[l * 10 + k];
                #pragma unroll
                for (int i = 0; i < 3; ++i) c[l][i] = fmaf(av, bk[i], c[l][i]);
            }
        }

        float ss = 0.0f;
        #pragma unroll
        for (int l = 0; l < 10; ++l)
            #pragma unroll
            for (int i = 0; i < 3; ++i)
                if (vld[i]) ss = fmaf(c[l][i], c[l][i], ss);
        #pragma unroll
        for (int off = 16; off >= 1; off >>= 1)
            if (off < L) ss += __shfl_xor_sync(gm, ss, off);

        ss = fmaxf(ss, 1e-24f);
        const float inv = rsqrtf(ss);
        if (lg == 0) logacc += 0.5f * __logf(ss);

        #pragma unroll
        for (int l = 0; l < 10; ++l)
            #pragma unroll
            for (int i = 0; i < 3; ++i)
                if (vld[i]) C[l * 10 + lg + i * L] = c[l][i] * inv;
        __syncwarp();
    }

    const float x0 = x[(size_t)b * NPIX];
    float wv = 0.0f;
    if (lane < 10) {
        #pragma unroll
        for (int l = 0; l < 10; ++l) {
            const float v0l = fmaf(x0, core0[10 + l] - core0[l], core0[l]);
            wv = fmaf(v0l, sG[w][6][l * 10 + lane], wv);
        }
    }
    float sq = (lane < 10) ? wv * wv : 0.0f;
    #pragma unroll
    for (int o = 16; o >= 1; o >>= 1) sq += __shfl_xor_sync(0xffffffffu, sq, o);
    #pragma unroll
    for (int o = 16; o >= 1; o >>= 1) logacc += __shfl_xor_sync(0xffffffffu, logacc, o);

    sq = fmaxf(sq, 1e-24f);
    const float logtot = logacc + 0.5f * __logf(sq);
    const float inv = rsqrtf(sq);
    if (lane < 10) sW[w][lane] = wv * inv;
    __syncwarp();

    if (lane < 10) {
        float acc = 0.0f;
        #pragma unroll
        for (int h = 0; h < 10; ++h) acc = fmaf(sW[w][h], cls[lane * 10 + h], acc);
        out[(size_t)b * 10 + lane] = acc + logtot;
    }
}

extern "C" void kernel_launch(void* const* d_in, const int* in_sizes, int n_in,
                              void* d_out, int out_size) {
    const float* x     = (const float*)d_in[0];   // (2048, 784)
    const float* core0 = (const float*)d_in[1];   // (1, 2, 10)
    const float* cm    = (const float*)d_in[2];   // (783, 10, 2, 10)
    const float* cls   = (const float*)d_in[3];   // (10, 10)
    float* out = (float*)d_out;                   // (2048, 10)

    dim3 g1(NSEG, BATCH / UPB);
    phase1<<<g1, T1>>>(x, cm);
    combine<<<BATCH / CB, CB * 32>>>(x, core0, cls, out);
}